// round 16
// baseline (speedup 1.0000x reference)
#include <cuda_runtime.h>
#include <cuda_fp16.h>
#include <math.h>
#include <stdint.h>

// ---------------------------------------------------------------- constants
#define T_TOK 8192
#define Dm    512
#define Fm    2048
#define Em    64
#define Hh    4
#define NC    256
#define CAP   1024
#define NSLOT (T_TOK * 2)

// routing fp32 GEMM tiling
#define BM 128
#define BN 128
#define BK 8

// mma FFN tiling: CTA 256m x 256n, 512 threads (4x4 warps, 64x64 warp tile),
// K-chunk 16, double-buffered smem, depth-2 register prefetch, plain fp16.
#define KCH   16
#define MT    256    // CTA M tile
#define SPAD  24     // A smem row stride (fp16): 16 k + 8 pad
#define BNP2  264    // B smem row stride (fp16): 256 n + 8 pad

// ---------------------------------------------------------------- scratch (~110MB)
__device__ __align__(256) float  g_logits[(size_t)T_TOK * NC];
__device__ __align__(256) int    g_count[Em];
__device__ __align__(256) int    g_toklist[Em * CAP];
__device__ __align__(256) __half g_hbuf[(size_t)NSLOT * Fm];
__device__ __align__(256) float  g_ybuf[(size_t)NSLOT * Dm];

// ---------------------------------------------------------------- helpers
__device__ __forceinline__ float gelu_exact(float v) {
    return 0.5f * v * (1.0f + erff(v * 0.7071067811865475f));
}
__device__ __forceinline__ uint32_t pack_h(__half a, __half b) {
    return (uint32_t)__half_as_ushort(a) | ((uint32_t)__half_as_ushort(b) << 16);
}
__device__ __forceinline__ uint2 hi4h(float4 v) {
    return make_uint2(pack_h(__float2half_rn(v.x), __float2half_rn(v.y)),
                      pack_h(__float2half_rn(v.z), __float2half_rn(v.w)));
}
__device__ __forceinline__ void mma_f16(float& d0, float& d1, float& d2, float& d3,
                                        uint32_t a0, uint32_t a1, uint32_t a2, uint32_t a3,
                                        uint32_t b0, uint32_t b1) {
    asm volatile(
        "mma.sync.aligned.m16n8k16.row.col.f32.f16.f16.f32 "
        "{%0,%1,%2,%3},{%4,%5,%6,%7},{%8,%9},{%0,%1,%2,%3};"
        : "+f"(d0), "+f"(d1), "+f"(d2), "+f"(d3)
        : "r"(a0), "r"(a1), "r"(a2), "r"(a3), "r"(b0), "r"(b1));
}
__device__ __forceinline__ void ldsm_x4(uint32_t& r0, uint32_t& r1, uint32_t& r2, uint32_t& r3,
                                        uint32_t addr) {
    asm volatile("ldmatrix.sync.aligned.m8n8.x4.shared.b16 {%0,%1,%2,%3}, [%4];"
                 : "=r"(r0), "=r"(r1), "=r"(r2), "=r"(r3) : "r"(addr));
}
__device__ __forceinline__ void ldsm_x4_t(uint32_t& r0, uint32_t& r1, uint32_t& r2, uint32_t& r3,
                                          uint32_t addr) {
    asm volatile("ldmatrix.sync.aligned.m8n8.x4.trans.shared.b16 {%0,%1,%2,%3}, [%4];"
                 : "=r"(r0), "=r"(r1), "=r"(r2), "=r"(r3) : "r"(addr));
}

// ---------------------------------------------------------------- K0: misc
__global__ void zc_kernel() {
    if (threadIdx.x < Em) g_count[threadIdx.x] = 0;
}

// ---------------------------------------------------------------- routing (proven, fp32-exact)
__global__ __launch_bounds__(256, 2)
void route_gemm(const float* __restrict__ x, const float* __restrict__ hp) {
    __shared__ float As[BK][BM + 4];
    __shared__ float Bs[BK][BN];
    const int tid = threadIdx.x;
    const int bm = blockIdx.y * BM;
    const int bn = blockIdx.x * BN;
    const int arow = tid >> 1, akq = (tid & 1) << 2;
    const int bkr = tid >> 5, bnq = (tid & 31) << 2;
    const int tx = tid & 15, ty = tid >> 4;

    const int c = bn + bnq;
    const float* bsrc = hp + (c >> 6) * (Dm * Em) + bkr * Em + (c & 63);
    const float* asrc = x + (size_t)(bm + arow) * Dm + akq;

    float acc[8][8];
#pragma unroll
    for (int i = 0; i < 8; i++)
#pragma unroll
        for (int j = 0; j < 8; j++) acc[i][j] = 0.0f;

    for (int k0 = 0; k0 < Dm; k0 += BK) {
        float4 av = *(const float4*)(asrc + k0);
        float4 bv = *(const float4*)(bsrc + (size_t)k0 * Em);
        As[akq + 0][arow] = av.x;
        As[akq + 1][arow] = av.y;
        As[akq + 2][arow] = av.z;
        As[akq + 3][arow] = av.w;
        *(float4*)&Bs[bkr][bnq] = bv;
        __syncthreads();
        float ar[8], br[8];
#pragma unroll
        for (int k = 0; k < BK; k++) {
            *(float4*)&ar[0] = *(const float4*)&As[k][ty * 4];
            *(float4*)&ar[4] = *(const float4*)&As[k][64 + ty * 4];
            *(float4*)&br[0] = *(const float4*)&Bs[k][tx * 4];
            *(float4*)&br[4] = *(const float4*)&Bs[k][64 + tx * 4];
#pragma unroll
            for (int i = 0; i < 8; i++)
#pragma unroll
                for (int j = 0; j < 8; j++)
                    acc[i][j] = fmaf(ar[i], br[j], acc[i][j]);
        }
        __syncthreads();
    }
#pragma unroll
    for (int i = 0; i < 8; i++) {
        int m = bm + ((i < 4) ? (ty * 4 + i) : (64 + ty * 4 + i - 4));
        float* dst = g_logits + (size_t)m * NC + bn;
        *(float4*)(dst + tx * 4)      = make_float4(acc[i][0], acc[i][1], acc[i][2], acc[i][3]);
        *(float4*)(dst + 64 + tx * 4) = make_float4(acc[i][4], acc[i][5], acc[i][6], acc[i][7]);
    }
}

// fused top-2 routing + dispatch
__global__ void route_top2_dispatch() {
    int t = (blockIdx.x * blockDim.x + threadIdx.x) >> 5;
    int lane = threadIdx.x & 31;
    if (t >= T_TOK) return;
    const float* lg = g_logits + (size_t)t * NC;
    float sc[Hh]; int cd[Hh];
#pragma unroll
    for (int h = 0; h < Hh; h++) {
        float v0 = lg[h * 64 + lane];
        float v1 = lg[h * 64 + 32 + lane];
        float v = v0; int idx = lane;
        if (v1 > v) { v = v1; idx = lane + 32; }
#pragma unroll
        for (int off = 16; off > 0; off >>= 1) {
            float ov = __shfl_xor_sync(0xffffffffu, v, off);
            int   oi = __shfl_xor_sync(0xffffffffu, idx, off);
            if (ov > v || (ov == v && oi < idx)) { v = ov; idx = oi; }
        }
        sc[h] = v; cd[h] = idx;
    }
    if (lane == 0) {
        int h1 = 0;
#pragma unroll
        for (int h = 1; h < Hh; h++) if (sc[h] > sc[h1]) h1 = h;
        int h2 = -1;
#pragma unroll
        for (int h = 0; h < Hh; h++) {
            if (h == h1) continue;
            if (h2 < 0 || sc[h] > sc[h2]) h2 = h;
        }
        int e0 = cd[h1], e1 = cd[h2];
        int p0 = atomicAdd(&g_count[e0], 1);
        if (p0 < CAP) g_toklist[e0 * CAP + p0] = t * 2;
        int p1 = atomicAdd(&g_count[e1], 1);
        if (p1 < CAP) g_toklist[e1 * CAP + p1] = t * 2 + 1;
    }
}

// ------------------------------------------------- mma.sync grouped GEMM
// Plain fp16. CTA 256m x 256n, 16 warps (4x4, warp tile 64x64), KCH=16,
// double-buffered static smem (41.5KB), depth-2 reg prefetch.
// F1: h[slot] = fp16(gelu(x @ W1[e]))     A fp32 -> cvt at STS
// F2: ybuf[slot] = h @ W2[e]              A fp16 raw (no cvt, half LDG)
template <bool F1>
__global__ __launch_bounds__(512, 1)
void moe_mma(const float* __restrict__ x, const float* __restrict__ W) {
    const int KTOT = F1 ? Dm : Fm;
    const int NTOT = F1 ? Fm : Dm;
    const int NKC  = KTOT / KCH;   // 32 / 128, even

    const int e = blockIdx.z;
    const int n_e = min(g_count[e], CAP);
    const int m0 = blockIdx.y * MT;
    if (m0 >= n_e) return;
    const int bn = blockIdx.x * 256;

    __shared__ __align__(16) __half sAh[2][MT * SPAD];
    __shared__ __align__(16) __half sBh[2][KCH * BNP2];
    __shared__ int stok[MT];

    const int tid  = threadIdx.x;
    const int lane = tid & 31;
    const int wid  = tid >> 5;
    const int wm   = wid & 3;       // warp M index (4)
    const int wn   = wid >> 2;      // warp N index (4)
    const int g    = lane >> 2;
    const int t2   = (lane & 3) * 2;

    if (tid < MT) {
        int r = m0 + tid;
        stok[tid] = (r < n_e) ? g_toklist[e * CAP + r] : 0;
    }
    __syncthreads();

    // producers: A row arow (0..255) x 8 k-elems (half ahalf); B k-row kr x 8 n
    const int arow  = tid >> 1;
    const int ahalf = tid & 1;
    const int aslot = stok[arow];
    const float*  arpf = F1 ? (x + (size_t)(aslot >> 1) * Dm + ahalf * 8) : nullptr;
    const __half* arph = F1 ? nullptr : (g_hbuf + (size_t)aslot * Fm + ahalf * 8);
    const int kr = tid >> 5;            // 0..15
    const int nq = (tid & 31) * 8;      // 0..248
    const float* wrp = W + (size_t)e * KTOT * NTOT + (size_t)kr * NTOT + bn + nq;

    float4 af0[2], af1[2];     // F1 A staging (fp32)
    uint4  ah0, ah1;           // F2 A staging (fp16 raw)
    float4 wr0[2], wr1[2];     // W staging

    auto ldg_chunk = [&](int kc, float4* af, uint4& ah, float4* wr) {
        if (F1) {
            const float4* ap = (const float4*)(arpf + kc * KCH);
            af[0] = ap[0];
            af[1] = ap[1];
        } else {
            ah = *(const uint4*)(arph + kc * KCH);
        }
        const float4* wk = (const float4*)(wrp + (size_t)kc * KCH * NTOT);
        wr[0] = wk[0];
        wr[1] = wk[1];
    };
    auto sts_chunk = [&](int s, const float4* af, const uint4& ah, const float4* wr) {
        char* pah = (char*)sAh[s] + (arow * SPAD + ahalf * 8) * 2;
        if (F1) {
            uint2 a0 = hi4h(af[0]), a1 = hi4h(af[1]);
            *(uint4*)pah = make_uint4(a0.x, a0.y, a1.x, a1.y);
        } else {
            *(uint4*)pah = ah;
        }
        uint2 b0 = hi4h(wr[0]), b1 = hi4h(wr[1]);
        *(uint4*)((char*)sBh[s] + (kr * BNP2 + nq) * 2) = make_uint4(b0.x, b0.y, b1.x, b1.y);
    };

    // consumer ldmatrix lane addressing (R9-R14 proven mappings)
    const int a_r = lane & 15;
    const int a_c = (lane >> 4) * 8;
    const int b_m  = lane >> 3;
    const int b_kr = (b_m & 1) * 8 + (lane & 7);
    const int b_n0 = wn * 64 + (b_m >> 1) * 8;

    float acc[4][8][4];
#pragma unroll
    for (int mi = 0; mi < 4; mi++)
#pragma unroll
        for (int ni = 0; ni < 8; ni++)
#pragma unroll
            for (int q = 0; q < 4; q++) acc[mi][ni][q] = 0.0f;

    auto compute = [&](int cur) {
        uint32_t ah[4][4], bh[8][2];
        uint32_t baseAh = (uint32_t)__cvta_generic_to_shared(sAh[cur]);
        uint32_t baseBh = (uint32_t)__cvta_generic_to_shared(sBh[cur]);
#pragma unroll
        for (int mi = 0; mi < 4; mi++) {
            uint32_t off = ((wm * 64 + mi * 16 + a_r) * SPAD + a_c) * 2;
            ldsm_x4(ah[mi][0], ah[mi][1], ah[mi][2], ah[mi][3], baseAh + off);
        }
#pragma unroll
        for (int np = 0; np < 4; np++) {
            uint32_t off = (b_kr * BNP2 + b_n0 + np * 16) * 2;
            ldsm_x4_t(bh[np * 2][0], bh[np * 2][1], bh[np * 2 + 1][0], bh[np * 2 + 1][1],
                      baseBh + off);
        }
#pragma unroll
        for (int mi = 0; mi < 4; mi++)
#pragma unroll
            for (int ni = 0; ni < 8; ni++) {
                float* d = acc[mi][ni];
                mma_f16(d[0], d[1], d[2], d[3],
                        ah[mi][0], ah[mi][1], ah[mi][2], ah[mi][3],
                        bh[ni][0], bh[ni][1]);
            }
    };

    // depth-2 pipeline
    ldg_chunk(0, af0, ah0, wr0);
    ldg_chunk(1, af1, ah1, wr1);

    for (int kc = 0; kc < NKC; kc += 2) {
        sts_chunk(0, af0, ah0, wr0);
        if (kc + 2 < NKC) ldg_chunk(kc + 2, af0, ah0, wr0);
        __syncthreads();
        compute(0);
        sts_chunk(1, af1, ah1, wr1);
        if (kc + 3 < NKC) ldg_chunk(kc + 3, af1, ah1, wr1);
        __syncthreads();
        compute(1);
    }

    // epilogue
#pragma unroll
    for (int mi = 0; mi < 4; mi++) {
#pragma unroll
        for (int half = 0; half < 2; half++) {
            int lr = wm * 64 + mi * 16 + g + half * 8;
            if (m0 + lr >= n_e) continue;
            int slot = stok[lr];
#pragma unroll
            for (int ni = 0; ni < 8; ni++) {
                int col = bn + wn * 64 + ni * 8 + t2;
                float v0 = acc[mi][ni][half * 2 + 0];
                float v1 = acc[mi][ni][half * 2 + 1];
                if (F1) {
                    v0 = gelu_exact(v0);
                    v1 = gelu_exact(v1);
                    *(uint32_t*)(g_hbuf + (size_t)slot * Fm + col) =
                        pack_h(__float2half_rn(v0), __float2half_rn(v1));
                } else {
                    *(float2*)(g_ybuf + (size_t)slot * Dm + col) = make_float2(v0, v1);
                }
            }
        }
    }
}

// ---------------------------------------------------------------- combine
__global__ void combine_kernel(float* __restrict__ out) {
    int i = blockIdx.x * 256 + threadIdx.x;     // float4 index
    if (i >= T_TOK * Dm / 4) return;
    int t = i >> 7;
    int c = i & 127;
    const float4* y = (const float4*)g_ybuf;
    float4 a = y[(size_t)(2 * t) * 128 + c];
    float4 b = y[(size_t)(2 * t + 1) * 128 + c];
    ((float4*)out)[i] = make_float4(0.5f * (a.x + b.x), 0.5f * (a.y + b.y),
                                    0.5f * (a.z + b.z), 0.5f * (a.w + b.w));
}

// ---------------------------------------------------------------- launcher
extern "C" void kernel_launch(void* const* d_in, const int* in_sizes, int n_in,
                              void* d_out, int out_size) {
    const float* x  = (const float*)d_in[0];
    const float* hp = (const float*)d_in[1];
    const float* W1 = (const float*)d_in[2];
    const float* W2 = (const float*)d_in[3];
    float* out = (float*)d_out;

    zc_kernel<<<1, 64>>>();
    route_gemm<<<dim3(NC / BN, T_TOK / BM), 256>>>(x, hp);
    route_top2_dispatch<<<(T_TOK * 32) / 256, 256>>>();
    moe_mma<true><<<dim3(Fm / 256, CAP / MT, Em), 512>>>(x, W1);
    moe_mma<false><<<dim3(Dm / 256, CAP / MT, Em), 512>>>(nullptr, W2);
    combine_kernel<<<(T_TOK * Dm / 4 + 255) / 256, 256>>>(out);
}

// round 17
// speedup vs baseline: 2.3948x; 2.3948x over previous
#include <cuda_runtime.h>
#include <cuda_fp16.h>
#include <math.h>
#include <stdint.h>

// ---------------------------------------------------------------- constants
#define T_TOK 8192
#define Dm    512
#define Fm    2048
#define Em    64
#define Hh    4
#define NC    256
#define CAP   1024
#define NSLOT (T_TOK * 2)

// routing fp32 GEMM tiling
#define BM 128
#define BN 128
#define BK 8

// mma FFN tiling: CTA 128m x 256n, 256 threads (2x4 warps, 64x64 warp tile),
// K-chunk 16, double-buffered smem, depth-2 register prefetch, plain fp16.
// (R14-proven structure; only change vs R14: g_hbuf is fp16.)
#define KCH   16
#define SPAD  24     // A smem row stride (fp16): 16 k + 8 pad
#define BNP2  264    // B smem row stride (fp16): 256 n + 8 pad

// ---------------------------------------------------------------- scratch (~110MB)
__device__ __align__(256) float  g_logits[(size_t)T_TOK * NC];
__device__ __align__(256) int    g_count[Em];
__device__ __align__(256) int    g_toklist[Em * CAP];
__device__ __align__(256) __half g_hbuf[(size_t)NSLOT * Fm];
__device__ __align__(256) float  g_ybuf[(size_t)NSLOT * Dm];

// ---------------------------------------------------------------- helpers
__device__ __forceinline__ float gelu_exact(float v) {
    return 0.5f * v * (1.0f + erff(v * 0.7071067811865475f));
}
__device__ __forceinline__ uint32_t pack_h(__half a, __half b) {
    return (uint32_t)__half_as_ushort(a) | ((uint32_t)__half_as_ushort(b) << 16);
}
__device__ __forceinline__ uint2 hi4h(float4 v) {
    return make_uint2(pack_h(__float2half_rn(v.x), __float2half_rn(v.y)),
                      pack_h(__float2half_rn(v.z), __float2half_rn(v.w)));
}
__device__ __forceinline__ void mma_f16(float& d0, float& d1, float& d2, float& d3,
                                        uint32_t a0, uint32_t a1, uint32_t a2, uint32_t a3,
                                        uint32_t b0, uint32_t b1) {
    asm volatile(
        "mma.sync.aligned.m16n8k16.row.col.f32.f16.f16.f32 "
        "{%0,%1,%2,%3},{%4,%5,%6,%7},{%8,%9},{%0,%1,%2,%3};"
        : "+f"(d0), "+f"(d1), "+f"(d2), "+f"(d3)
        : "r"(a0), "r"(a1), "r"(a2), "r"(a3), "r"(b0), "r"(b1));
}
__device__ __forceinline__ void ldsm_x4(uint32_t& r0, uint32_t& r1, uint32_t& r2, uint32_t& r3,
                                        uint32_t addr) {
    asm volatile("ldmatrix.sync.aligned.m8n8.x4.shared.b16 {%0,%1,%2,%3}, [%4];"
                 : "=r"(r0), "=r"(r1), "=r"(r2), "=r"(r3) : "r"(addr));
}
__device__ __forceinline__ void ldsm_x4_t(uint32_t& r0, uint32_t& r1, uint32_t& r2, uint32_t& r3,
                                          uint32_t addr) {
    asm volatile("ldmatrix.sync.aligned.m8n8.x4.trans.shared.b16 {%0,%1,%2,%3}, [%4];"
                 : "=r"(r0), "=r"(r1), "=r"(r2), "=r"(r3) : "r"(addr));
}

// ---------------------------------------------------------------- K0: misc
__global__ void zc_kernel() {
    if (threadIdx.x < Em) g_count[threadIdx.x] = 0;
}

// ---------------------------------------------------------------- routing (proven, fp32-exact)
__global__ __launch_bounds__(256, 2)
void route_gemm(const float* __restrict__ x, const float* __restrict__ hp) {
    __shared__ float As[BK][BM + 4];
    __shared__ float Bs[BK][BN];
    const int tid = threadIdx.x;
    const int bm = blockIdx.y * BM;
    const int bn = blockIdx.x * BN;
    const int arow = tid >> 1, akq = (tid & 1) << 2;
    const int bkr = tid >> 5, bnq = (tid & 31) << 2;
    const int tx = tid & 15, ty = tid >> 4;

    const int c = bn + bnq;
    const float* bsrc = hp + (c >> 6) * (Dm * Em) + bkr * Em + (c & 63);
    const float* asrc = x + (size_t)(bm + arow) * Dm + akq;

    float acc[8][8];
#pragma unroll
    for (int i = 0; i < 8; i++)
#pragma unroll
        for (int j = 0; j < 8; j++) acc[i][j] = 0.0f;

    for (int k0 = 0; k0 < Dm; k0 += BK) {
        float4 av = *(const float4*)(asrc + k0);
        float4 bv = *(const float4*)(bsrc + (size_t)k0 * Em);
        As[akq + 0][arow] = av.x;
        As[akq + 1][arow] = av.y;
        As[akq + 2][arow] = av.z;
        As[akq + 3][arow] = av.w;
        *(float4*)&Bs[bkr][bnq] = bv;
        __syncthreads();
        float ar[8], br[8];
#pragma unroll
        for (int k = 0; k < BK; k++) {
            *(float4*)&ar[0] = *(const float4*)&As[k][ty * 4];
            *(float4*)&ar[4] = *(const float4*)&As[k][64 + ty * 4];
            *(float4*)&br[0] = *(const float4*)&Bs[k][tx * 4];
            *(float4*)&br[4] = *(const float4*)&Bs[k][64 + tx * 4];
#pragma unroll
            for (int i = 0; i < 8; i++)
#pragma unroll
                for (int j = 0; j < 8; j++)
                    acc[i][j] = fmaf(ar[i], br[j], acc[i][j]);
        }
        __syncthreads();
    }
#pragma unroll
    for (int i = 0; i < 8; i++) {
        int m = bm + ((i < 4) ? (ty * 4 + i) : (64 + ty * 4 + i - 4));
        float* dst = g_logits + (size_t)m * NC + bn;
        *(float4*)(dst + tx * 4)      = make_float4(acc[i][0], acc[i][1], acc[i][2], acc[i][3]);
        *(float4*)(dst + 64 + tx * 4) = make_float4(acc[i][4], acc[i][5], acc[i][6], acc[i][7]);
    }
}

// fused top-2 routing + dispatch
__global__ void route_top2_dispatch() {
    int t = (blockIdx.x * blockDim.x + threadIdx.x) >> 5;
    int lane = threadIdx.x & 31;
    if (t >= T_TOK) return;
    const float* lg = g_logits + (size_t)t * NC;
    float sc[Hh]; int cd[Hh];
#pragma unroll
    for (int h = 0; h < Hh; h++) {
        float v0 = lg[h * 64 + lane];
        float v1 = lg[h * 64 + 32 + lane];
        float v = v0; int idx = lane;
        if (v1 > v) { v = v1; idx = lane + 32; }
#pragma unroll
        for (int off = 16; off > 0; off >>= 1) {
            float ov = __shfl_xor_sync(0xffffffffu, v, off);
            int   oi = __shfl_xor_sync(0xffffffffu, idx, off);
            if (ov > v || (ov == v && oi < idx)) { v = ov; idx = oi; }
        }
        sc[h] = v; cd[h] = idx;
    }
    if (lane == 0) {
        int h1 = 0;
#pragma unroll
        for (int h = 1; h < Hh; h++) if (sc[h] > sc[h1]) h1 = h;
        int h2 = -1;
#pragma unroll
        for (int h = 0; h < Hh; h++) {
            if (h == h1) continue;
            if (h2 < 0 || sc[h] > sc[h2]) h2 = h;
        }
        int e0 = cd[h1], e1 = cd[h2];
        int p0 = atomicAdd(&g_count[e0], 1);
        if (p0 < CAP) g_toklist[e0 * CAP + p0] = t * 2;
        int p1 = atomicAdd(&g_count[e1], 1);
        if (p1 < CAP) g_toklist[e1 * CAP + p1] = t * 2 + 1;
    }
}

// ------------------------------------------------- mma.sync grouped GEMM
// Plain fp16. CTA 128m x 256n, 8 warps (2x4, warp tile 64x64), KCH=16,
// double-buffered static smem, depth-2 reg prefetch. (R14-proven, 256 thr.)
// F1: h[slot] = fp16(gelu(x @ W1[e]))     A fp32 -> cvt at STS
// F2: ybuf[slot] = h @ W2[e]              A fp16 raw copy (no cvt)
template <bool F1>
__global__ __launch_bounds__(256, 1)
void moe_mma(const float* __restrict__ x, const float* __restrict__ W) {
    const int KTOT = F1 ? Dm : Fm;
    const int NTOT = F1 ? Fm : Dm;
    const int NKC  = KTOT / KCH;   // 32 / 128, even

    const int e = blockIdx.z;
    const int n_e = min(g_count[e], CAP);
    const int m0 = blockIdx.y * 128;
    if (m0 >= n_e) return;
    const int bn = blockIdx.x * 256;

    __shared__ __align__(16) __half sAh[2][128 * SPAD];
    __shared__ __align__(16) __half sBh[2][KCH * BNP2];
    __shared__ int stok[128];

    const int tid  = threadIdx.x;
    const int lane = tid & 31;
    const int wid  = tid >> 5;
    const int wm   = wid & 1;       // warp M index (2)
    const int wn   = wid >> 1;      // warp N index (4)
    const int g    = lane >> 2;
    const int t2   = (lane & 3) * 2;

    if (tid < 128) {
        int r = m0 + tid;
        stok[tid] = (r < n_e) ? g_toklist[e * CAP + r] : 0;
    }
    __syncthreads();

    // producers: A row arow (0..127) x 8 k-elems (half ahalf); B k-row kr x 16 n
    const int arow  = tid >> 1;
    const int ahalf = tid & 1;
    const int aslot = stok[arow];
    const float*  arpf = F1 ? (x + (size_t)(aslot >> 1) * Dm + ahalf * 8) : nullptr;
    const __half* arph = F1 ? nullptr : (g_hbuf + (size_t)aslot * Fm + ahalf * 8);
    const int kr = tid >> 4;
    const int nq = (tid & 15) * 16;
    const float* wrp = W + (size_t)e * KTOT * NTOT + (size_t)kr * NTOT + bn + nq;

    float4 af0[2], af1[2];     // F1 A staging (fp32)
    uint4  ah0, ah1;           // F2 A staging (fp16 raw)
    float4 wreg0[4], wreg1[4];

    auto ldg_chunk = [&](int kc, float4* af, uint4& ah, float4* wr) {
        if (F1) {
            const float4* ap = (const float4*)(arpf + kc * KCH);
            af[0] = ap[0];
            af[1] = ap[1];
        } else {
            ah = *(const uint4*)(arph + kc * KCH);
        }
        const float4* wk = (const float4*)(wrp + (size_t)kc * KCH * NTOT);
#pragma unroll
        for (int j = 0; j < 4; j++) wr[j] = wk[j];
    };
    auto sts_chunk = [&](int s, const float4* af, const uint4& ah, const float4* wr) {
        char* pah = (char*)sAh[s] + (arow * SPAD + ahalf * 8) * 2;
        if (F1) {
            uint2 a0 = hi4h(af[0]), a1 = hi4h(af[1]);
            *(uint4*)pah = make_uint4(a0.x, a0.y, a1.x, a1.y);
        } else {
            *(uint4*)pah = ah;
        }
        uint2 b0 = hi4h(wr[0]), b1 = hi4h(wr[1]), b2 = hi4h(wr[2]), b3 = hi4h(wr[3]);
        char* pb = (char*)sBh[s] + (kr * BNP2 + nq) * 2;
        *(uint4*)(pb)      = make_uint4(b0.x, b0.y, b1.x, b1.y);
        *(uint4*)(pb + 16) = make_uint4(b2.x, b2.y, b3.x, b3.y);
    };

    // consumer ldmatrix lane addressing (R9-R14 proven mappings)
    const int a_r = lane & 15;
    const int a_c = (lane >> 4) * 8;
    const int b_m  = lane >> 3;
    const int b_kr = (b_m & 1) * 8 + (lane & 7);
    const int b_n0 = wn * 64 + (b_m >> 1) * 8;

    float acc[4][8][4];
#pragma unroll
    for (int mi = 0; mi < 4; mi++)
#pragma unroll
        for (int ni = 0; ni < 8; ni++)
#pragma unroll
            for (int q = 0; q < 4; q++) acc[mi][ni][q] = 0.0f;

    auto compute = [&](int cur) {
        uint32_t ah[4][4], bh[8][2];
        uint32_t baseAh = (uint32_t)__cvta_generic_to_shared(sAh[cur]);
        uint32_t baseBh = (uint32_t)__cvta_generic_to_shared(sBh[cur]);
#pragma unroll
        for (int mi = 0; mi < 4; mi++) {
            uint32_t off = ((wm * 64 + mi * 16 + a_r) * SPAD + a_c) * 2;
            ldsm_x4(ah[mi][0], ah[mi][1], ah[mi][2], ah[mi][3], baseAh + off);
        }
#pragma unroll
        for (int np = 0; np < 4; np++) {
            uint32_t off = (b_kr * BNP2 + b_n0 + np * 16) * 2;
            ldsm_x4_t(bh[np * 2][0], bh[np * 2][1], bh[np * 2 + 1][0], bh[np * 2 + 1][1],
                      baseBh + off);
        }
#pragma unroll
        for (int mi = 0; mi < 4; mi++)
#pragma unroll
            for (int ni = 0; ni < 8; ni++) {
                float* d = acc[mi][ni];
                mma_f16(d[0], d[1], d[2], d[3],
                        ah[mi][0], ah[mi][1], ah[mi][2], ah[mi][3],
                        bh[ni][0], bh[ni][1]);
            }
    };

    // depth-2 pipeline
    ldg_chunk(0, af0, ah0, wreg0);
    ldg_chunk(1, af1, ah1, wreg1);

    for (int kc = 0; kc < NKC; kc += 2) {
        sts_chunk(0, af0, ah0, wreg0);
        if (kc + 2 < NKC) ldg_chunk(kc + 2, af0, ah0, wreg0);
        __syncthreads();
        compute(0);
        sts_chunk(1, af1, ah1, wreg1);
        if (kc + 3 < NKC) ldg_chunk(kc + 3, af1, ah1, wreg1);
        __syncthreads();
        compute(1);
    }

    // epilogue (proven layout)
#pragma unroll
    for (int mi = 0; mi < 4; mi++) {
#pragma unroll
        for (int half = 0; half < 2; half++) {
            int lr = wm * 64 + mi * 16 + g + half * 8;
            if (m0 + lr >= n_e) continue;
            int slot = stok[lr];
#pragma unroll
            for (int ni = 0; ni < 8; ni++) {
                int col = bn + wn * 64 + ni * 8 + t2;
                float v0 = acc[mi][ni][half * 2 + 0];
                float v1 = acc[mi][ni][half * 2 + 1];
                if (F1) {
                    v0 = gelu_exact(v0);
                    v1 = gelu_exact(v1);
                    *(uint32_t*)(g_hbuf + (size_t)slot * Fm + col) =
                        pack_h(__float2half_rn(v0), __float2half_rn(v1));
                } else {
                    *(float2*)(g_ybuf + (size_t)slot * Dm + col) = make_float2(v0, v1);
                }
            }
        }
    }
}

// ---------------------------------------------------------------- combine
__global__ void combine_kernel(float* __restrict__ out) {
    int i = blockIdx.x * 256 + threadIdx.x;     // float4 index
    if (i >= T_TOK * Dm / 4) return;
    int t = i >> 7;
    int c = i & 127;
    const float4* y = (const float4*)g_ybuf;
    float4 a = y[(size_t)(2 * t) * 128 + c];
    float4 b = y[(size_t)(2 * t + 1) * 128 + c];
    ((float4*)out)[i] = make_float4(0.5f * (a.x + b.x), 0.5f * (a.y + b.y),
                                    0.5f * (a.z + b.z), 0.5f * (a.w + b.w));
}

// ---------------------------------------------------------------- launcher
extern "C" void kernel_launch(void* const* d_in, const int* in_sizes, int n_in,
                              void* d_out, int out_size) {
    const float* x  = (const float*)d_in[0];
    const float* hp = (const float*)d_in[1];
    const float* W1 = (const float*)d_in[2];
    const float* W2 = (const float*)d_in[3];
    float* out = (float*)d_out;

    zc_kernel<<<1, 64>>>();
    route_gemm<<<dim3(NC / BN, T_TOK / BM), 256>>>(x, hp);
    route_top2_dispatch<<<(T_TOK * 32) / 256, 256>>>();
    moe_mma<true><<<dim3(Fm / 256, CAP / 128, Em), 256>>>(x, W1);
    moe_mma<false><<<dim3(Dm / 256, CAP / 128, Em), 256>>>(nullptr, W2);
    combine_kernel<<<(T_TOK * Dm / 4 + 255) / 256, 256>>>(out);
}